// round 16
// baseline (speedup 1.0000x reference)
#include <cuda_runtime.h>
#include <math.h>

#define D_MODEL 1024
#define T_FULL 512
#define BATCH 2
#define ROWS (BATCH * T_FULL)   /* 1024 */
#define D_FF 2816
#define IN_FEAT 64
#define NHEAD 16
#define HD 64
#define HD2 32
#define EPS_DEF 1.1920928955078125e-07f
#define EPS_HEAD 1e-05f

typedef unsigned long long ull;

// ---------------- packed f32x2 helpers (sm_103a FFMA2 path) -----------------------
__device__ __forceinline__ ull ffma2(ull a, ull b, ull c) {
    ull r; asm("fma.rn.f32x2 %0, %1, %2, %3;" : "=l"(r) : "l"(a), "l"(b), "l"(c)); return r;
}
__device__ __forceinline__ ull fmul2(ull a, ull b) {
    ull r; asm("mul.rn.f32x2 %0, %1, %2;" : "=l"(r) : "l"(a), "l"(b)); return r;
}
__device__ __forceinline__ ull fadd2(ull a, ull b) {
    ull r; asm("add.rn.f32x2 %0, %1, %2;" : "=l"(r) : "l"(a), "l"(b)); return r;
}
__device__ __forceinline__ ull fpack2(float lo, float hi) {
    ull r; asm("mov.b64 %0, {%1, %2};" : "=l"(r) : "f"(lo), "f"(hi)); return r;
}
__device__ __forceinline__ float2 funpack2(ull v) {
    float2 f; asm("mov.b64 {%0, %1}, %2;" : "=f"(f.x), "=f"(f.y) : "l"(v)); return f;
}

// ---------------- scratch (device globals; no allocation allowed) ----------------
__device__ float g_h [ROWS * D_MODEL];
__device__ float g_q [ROWS * D_MODEL];
__device__ float g_k [ROWS * D_MODEL];
__device__ float g_v [ROWS * D_MODEL];
__device__ float g_y [ROWS * D_MODEL];
__device__ float g_act[ROWS * D_FF];
__device__ float g_rinv[ROWS];

// ---------------- embed ----------------------------------------------------------
__global__ void embed_kernel(const float* __restrict__ x, const int* __restrict__ sep,
                             const float* __restrict__ sep_emb,
                             const float* __restrict__ Wi, const float* __restrict__ bi) {
    int row = blockIdx.x;
    int b = row >> 9;
    int t = row & 511;
    const float inv = 0.03125f; // 1/sqrt(1024)
    if (t == 0) {
        int idx = sep[b];
        for (int d = threadIdx.x; d < D_MODEL; d += blockDim.x)
            g_h[row * D_MODEL + d] = sep_emb[idx * D_MODEL + d] * inv;
        return;
    }
    __shared__ float xs[IN_FEAT];
    if (threadIdx.x < IN_FEAT)
        xs[threadIdx.x] = x[(b * 511 + (t - 1)) * IN_FEAT + threadIdx.x];
    __syncthreads();
    for (int d = threadIdx.x; d < D_MODEL; d += blockDim.x) {
        float acc = bi[d];
        const float* wr = Wi + d * IN_FEAT;
#pragma unroll
        for (int f = 0; f < IN_FEAT; f++) acc += xs[f] * wr[f];
        g_h[row * D_MODEL + d] = acc * inv;
    }
}

// ---------------- RMS row-statistic: rinv[row] = rsqrt(mean(h^2)+eps) -------------
__global__ void rms_stat(const float* __restrict__ in, float* __restrict__ rinv, float eps) {
    int row = blockIdx.x;
    int t = threadIdx.x;
    const float4* inr = (const float4*)(in + (size_t)row * D_MODEL);
    __shared__ float red[256];
    float ss = 0.f;
    for (int i = t; i < D_MODEL / 4; i += 256) {
        float4 v = inr[i];
        ss += v.x * v.x + v.y * v.y + v.z * v.z + v.w * v.w;
    }
    red[t] = ss;
    __syncthreads();
    for (int s = 128; s > 0; s >>= 1) {
        if (t < s) red[t] += red[t + s];
        __syncthreads();
    }
    if (t == 0) rinv[row] = rsqrtf(red[0] / (float)D_MODEL + eps);
}

// ---------------- TF32 tensor-core GEMM (single-buffered, R9-proven) --------------
#define BK 32
#define BKP 36

__device__ __forceinline__ unsigned f2tf32(float x) {
    unsigned y;
    asm("cvt.rna.tf32.f32 %0, %1;" : "=r"(y) : "f"(x));
    return y;
}

// C[M,N] = rinv[m]*((A∘nw)[M,K] @ W[N,K]^T) + bias (+C if accum); optional RoPE.
// do_norm: nw fused at tile load (vectorized); rinv applied in EPILOGUE (per-row
// scalar hoisted out of the K-reduction — keeps the load pipeline clean).
template <int TBM, int TBN, int NT>
__device__ __forceinline__ void gemm_body(
    const float* __restrict__ A, const float* __restrict__ W,
    const float* __restrict__ bias, float* __restrict__ C,
    int N, int K, int accum, int bm, int bn,
    int do_rope, const float* __restrict__ cosb, const float* __restrict__ sinb,
    int do_norm, const float* __restrict__ rinv, const float* __restrict__ nw) {
    __shared__ unsigned As[TBM * BKP];
    __shared__ unsigned Ws[TBN * BKP];

    constexpr int WN  = TBN / 32;           // warps along n
    constexpr int AIT = TBM * 8 / NT;       // A load iters (float4)
    constexpr int BIT = TBN * 8 / NT;       // B load iters

    const int tid  = threadIdx.x;
    const int lane = tid & 31;
    const int wid  = tid >> 5;
    const int wm   = wid / WN;
    const int wn   = wid % WN;
    const int gid  = lane >> 2;
    const int tig  = lane & 3;

    float acc[2][4][4];
#pragma unroll
    for (int mt = 0; mt < 2; mt++)
#pragma unroll
        for (int nt = 0; nt < 4; nt++)
#pragma unroll
            for (int r = 0; r < 4; r++) acc[mt][nt][r] = 0.f;

    float4 ra[AIT], rb[BIT];
    const int pcol = (tid & 7) * 4;

    auto ldg_tile = [&](int k0) {
        float4 wv;
        if (do_norm) wv = *(const float4*)(nw + k0 + pcol);
#pragma unroll
        for (int i = 0; i < AIT; i++) {
            int r = (tid + i * NT) >> 3;
            ra[i] = *(const float4*)(A + (size_t)(bm + r) * K + k0 + pcol);
            if (do_norm) {
                ra[i].x *= wv.x; ra[i].y *= wv.y;
                ra[i].z *= wv.z; ra[i].w *= wv.w;
            }
        }
#pragma unroll
        for (int i = 0; i < BIT; i++) {
            int r = (tid + i * NT) >> 3;
            rb[i] = *(const float4*)(W + (size_t)(bn + r) * K + k0 + pcol);
        }
    };
    auto sts_tile = [&]() {
#pragma unroll
        for (int i = 0; i < AIT; i++) {
            int r = (tid + i * NT) >> 3;
            uint4 u = { f2tf32(ra[i].x), f2tf32(ra[i].y), f2tf32(ra[i].z), f2tf32(ra[i].w) };
            *(uint4*)&As[r * BKP + pcol] = u;
        }
#pragma unroll
        for (int i = 0; i < BIT; i++) {
            int r = (tid + i * NT) >> 3;
            uint4 u = { f2tf32(rb[i].x), f2tf32(rb[i].y), f2tf32(rb[i].z), f2tf32(rb[i].w) };
            *(uint4*)&Ws[r * BKP + pcol] = u;
        }
    };

    ldg_tile(0);
    sts_tile();
    __syncthreads();

    const int nit = K / BK;
    for (int it = 0; it < nit; it++) {
        if (it + 1 < nit) ldg_tile((it + 1) * BK);

#pragma unroll
        for (int ks = 0; ks < 4; ks++) {
            const int k = ks * 8;
            unsigned af[2][4], bf[4][2];
#pragma unroll
            for (int mt = 0; mt < 2; mt++) {
                int r = wm * 32 + mt * 16 + gid;
                af[mt][0] = As[r * BKP + k + tig];
                af[mt][1] = As[(r + 8) * BKP + k + tig];
                af[mt][2] = As[r * BKP + k + tig + 4];
                af[mt][3] = As[(r + 8) * BKP + k + tig + 4];
            }
#pragma unroll
            for (int nt = 0; nt < 4; nt++) {
                int c = wn * 32 + nt * 8 + gid;
                bf[nt][0] = Ws[c * BKP + k + tig];
                bf[nt][1] = Ws[c * BKP + k + tig + 4];
            }
#pragma unroll
            for (int mt = 0; mt < 2; mt++)
#pragma unroll
                for (int nt = 0; nt < 4; nt++) {
                    asm volatile(
                        "mma.sync.aligned.m16n8k8.row.col.f32.tf32.tf32.f32 "
                        "{%0,%1,%2,%3}, {%4,%5,%6,%7}, {%8,%9}, {%0,%1,%2,%3};\n"
                        : "+f"(acc[mt][nt][0]), "+f"(acc[mt][nt][1]),
                          "+f"(acc[mt][nt][2]), "+f"(acc[mt][nt][3])
                        : "r"(af[mt][0]), "r"(af[mt][1]), "r"(af[mt][2]), "r"(af[mt][3]),
                          "r"(bf[nt][0]), "r"(bf[nt][1]));
                }
        }
        __syncthreads();
        if (it + 1 < nit) {
            sts_tile();
            __syncthreads();
        }
    }

#pragma unroll
    for (int mt = 0; mt < 2; mt++) {
        int r0 = bm + wm * 32 + mt * 16 + gid;
        float rv0 = 1.f, rv1 = 1.f;
        if (do_norm) { rv0 = rinv[r0]; rv1 = rinv[r0 + 8]; }
#pragma unroll
        for (int nt = 0; nt < 4; nt++) {
            int c0 = bn + wn * 32 + nt * 8 + 2 * tig;
            float2 b2 = *(const float2*)(bias + c0);
            float* p0 = C + (size_t)r0 * N + c0;
            float* p1 = C + (size_t)(r0 + 8) * N + c0;
            float2 v0 = { acc[mt][nt][0] * rv0 + b2.x, acc[mt][nt][1] * rv0 + b2.y };
            float2 v1 = { acc[mt][nt][2] * rv1 + b2.x, acc[mt][nt][3] * rv1 + b2.y };
            if (accum) {
                float2 o0 = *(float2*)p0, o1 = *(float2*)p1;
                v0.x += o0.x; v0.y += o0.y;
                v1.x += o1.x; v1.y += o1.y;
            }
            if (do_rope) {
                int i = (c0 & 31) >> 1;    // pair index within sub-head
                int t0 = r0 & 511;
                if (t0 > 0) {
                    float cc = cosb[(t0 - 1) * 16 + i], ss = sinb[(t0 - 1) * 16 + i];
                    float xr = v0.x, xi = v0.y;
                    v0.x = xr * cc - xi * ss;
                    v0.y = xr * ss + xi * cc;
                }
                int t1 = (r0 + 8) & 511;
                if (t1 > 0) {
                    float cc = cosb[(t1 - 1) * 16 + i], ss = sinb[(t1 - 1) * 16 + i];
                    float xr = v1.x, xi = v1.y;
                    v1.x = xr * cc - xi * ss;
                    v1.y = xr * ss + xi * cc;
                }
            }
            *(float2*)p0 = v0;
            *(float2*)p1 = v1;
        }
    }
}

// 128x64 tile, 256 threads — QKV with fused input RMSNorm + output RoPE
__global__ void __launch_bounds__(256)
gemm_qkv(const float* __restrict__ A,
         const float* __restrict__ Wq, const float* __restrict__ Wk, const float* __restrict__ Wv,
         const float* __restrict__ bq, const float* __restrict__ bk, const float* __restrict__ bv,
         const float* __restrict__ cosb, const float* __restrict__ sinb,
         const float* __restrict__ rinv, const float* __restrict__ n1w) {
    const int seg = blockIdx.x >> 4;               // 0..2
    const int bn = (blockIdx.x & 15) * 64;
    const float* W   = (seg == 0) ? Wq : (seg == 1) ? Wk : Wv;
    const float* bia = (seg == 0) ? bq : (seg == 1) ? bk : bv;
    float* C = (seg == 0) ? g_q : (seg == 1) ? g_k : g_v;
    gemm_body<128, 64, 256>(A, W, bia, C, D_MODEL, D_MODEL, 0, blockIdx.y * 128, bn,
                            (seg < 2) ? 1 : 0, cosb, sinb, 1, rinv, n1w);
}

// 64x64 tile, 128 threads — Wo/Wf (grid 256 > SM count)
__global__ void __launch_bounds__(128)
gemm_small(const float* __restrict__ A, const float* __restrict__ W,
           const float* __restrict__ bias, float* __restrict__ C,
           int N, int K, int accum) {
    gemm_body<64, 64, 128>(A, W, bias, C, N, K, accum, blockIdx.y * 64, blockIdx.x * 64,
                           0, (const float*)0, (const float*)0,
                           0, (const float*)0, (const float*)0);
}

// ---------------- fused FFN-1 (input RMSNorm + u*silu(g)) -------------------------
// nw fused at load (vectorized); rinv applied to accU/accG in the epilogue.
__global__ void __launch_bounds__(128)
gemm_ffn1(const float* __restrict__ A, const float* __restrict__ Wg_,
          const float* __restrict__ bg_,
          const float* __restrict__ rinv, const float* __restrict__ n2w) {
    __shared__ unsigned As[64 * BKP];
    __shared__ unsigned Us[64 * BKP];
    __shared__ unsigned Gs[64 * BKP];

    const int tid  = threadIdx.x;
    const int lane = tid & 31;
    const int wid  = tid >> 5;
    const int wm   = wid >> 1;
    const int wn   = wid & 1;
    const int gid  = lane >> 2;
    const int tig  = lane & 3;
    const int bm   = blockIdx.y * 64;
    const int bn   = blockIdx.x * 64;

    float accU[2][4][4], accG[2][4][4];
#pragma unroll
    for (int mt = 0; mt < 2; mt++)
#pragma unroll
        for (int nt = 0; nt < 4; nt++)
#pragma unroll
            for (int r = 0; r < 4; r++) { accU[mt][nt][r] = 0.f; accG[mt][nt][r] = 0.f; }

    float4 ra[4], ru[4], rg[4];
    const int pcol = (tid & 7) * 4;

    auto ldg_tile = [&](int k0) {
        float4 wv = *(const float4*)(n2w + k0 + pcol);
#pragma unroll
        for (int i = 0; i < 4; i++) {
            int r = (tid + i * 128) >> 3;
            ra[i] = *(const float4*)(A   + (size_t)(bm + r) * D_MODEL + k0 + pcol);
            ra[i].x *= wv.x; ra[i].y *= wv.y;
            ra[i].z *= wv.z; ra[i].w *= wv.w;
            ru[i] = *(const float4*)(Wg_ + (size_t)(bn + r) * D_MODEL + k0 + pcol);
            rg[i] = *(const float4*)(Wg_ + (size_t)(D_FF + bn + r) * D_MODEL + k0 + pcol);
        }
    };
    auto sts_tile = [&]() {
#pragma unroll
        for (int i = 0; i < 4; i++) {
            int r = (tid + i * 128) >> 3;
            uint4 ua = { f2tf32(ra[i].x), f2tf32(ra[i].y), f2tf32(ra[i].z), f2tf32(ra[i].w) };
            *(uint4*)&As[r * BKP + pcol] = ua;
            uint4 uu = { f2tf32(ru[i].x), f2tf32(ru[i].y), f2tf32(ru[i].z), f2tf32(ru[i].w) };
            *(uint4*)&Us[r * BKP + pcol] = uu;
            uint4 ug = { f2tf32(rg[i].x), f2tf32(rg[i].y), f2tf32(rg[i].z), f2tf32(rg[i].w) };
            *(uint4*)&Gs[r * BKP + pcol] = ug;
        }
    };

    ldg_tile(0);
    sts_tile();
    __syncthreads();

    const int nit = D_MODEL / BK;   // 32
    for (int it = 0; it < nit; it++) {
        if (it + 1 < nit) ldg_tile((it + 1) * BK);

#pragma unroll
        for (int ks = 0; ks < 4; ks++) {
            const int k = ks * 8;
            unsigned af[2][4], bu[4][2], bg2[4][2];
#pragma unroll
            for (int mt = 0; mt < 2; mt++) {
                int r = wm * 32 + mt * 16 + gid;
                af[mt][0] = As[r * BKP + k + tig];
                af[mt][1] = As[(r + 8) * BKP + k + tig];
                af[mt][2] = As[r * BKP + k + tig + 4];
                af[mt][3] = As[(r + 8) * BKP + k + tig + 4];
            }
#pragma unroll
            for (int nt = 0; nt < 4; nt++) {
                int c = wn * 32 + nt * 8 + gid;
                bu[nt][0]  = Us[c * BKP + k + tig];
                bu[nt][1]  = Us[c * BKP + k + tig + 4];
                bg2[nt][0] = Gs[c * BKP + k + tig];
                bg2[nt][1] = Gs[c * BKP + k + tig + 4];
            }
#pragma unroll
            for (int mt = 0; mt < 2; mt++)
#pragma unroll
                for (int nt = 0; nt < 4; nt++) {
                    asm volatile(
                        "mma.sync.aligned.m16n8k8.row.col.f32.tf32.tf32.f32 "
                        "{%0,%1,%2,%3}, {%4,%5,%6,%7}, {%8,%9}, {%0,%1,%2,%3};\n"
                        : "+f"(accU[mt][nt][0]), "+f"(accU[mt][nt][1]),
                          "+f"(accU[mt][nt][2]), "+f"(accU[mt][nt][3])
                        : "r"(af[mt][0]), "r"(af[mt][1]), "r"(af[mt][2]), "r"(af[mt][3]),
                          "r"(bu[nt][0]), "r"(bu[nt][1]));
                    asm volatile(
                        "mma.sync.aligned.m16n8k8.row.col.f32.tf32.tf32.f32 "
                        "{%0,%1,%2,%3}, {%4,%5,%6,%7}, {%8,%9}, {%0,%1,%2,%3};\n"
                        : "+f"(accG[mt][nt][0]), "+f"(accG[mt][nt][1]),
                          "+f"(accG[mt][nt][2]), "+f"(accG[mt][nt][3])
                        : "r"(af[mt][0]), "r"(af[mt][1]), "r"(af[mt][2]), "r"(af[mt][3]),
                          "r"(bg2[nt][0]), "r"(bg2[nt][1]));
                }
        }
        __syncthreads();
        if (it + 1 < nit) {
            sts_tile();
            __syncthreads();
        }
    }

#pragma unroll
    for (int mt = 0; mt < 2; mt++) {
        int r0 = bm + wm * 32 + mt * 16 + gid;
        float rv0 = rinv[r0], rv1 = rinv[r0 + 8];
#pragma unroll
        for (int nt = 0; nt < 4; nt++) {
            int c0 = bn + wn * 32 + nt * 8 + 2 * tig;
            float2 bU = *(const float2*)(bg_ + c0);
            float2 bG = *(const float2*)(bg_ + D_FF + c0);
#pragma unroll
            for (int half = 0; half < 2; half++) {
                int rr = r0 + half * 8;
                float rv = half ? rv1 : rv0;
                float u0 = accU[mt][nt][2 * half + 0] * rv + bU.x;
                float u1 = accU[mt][nt][2 * half + 1] * rv + bU.y;
                float gg0 = accG[mt][nt][2 * half + 0] * rv + bG.x;
                float gg1 = accG[mt][nt][2 * half + 1] * rv + bG.y;
                float2 o;
                o.x = u0 * (gg0 / (1.f + __expf(-gg0)));
                o.y = u1 * (gg1 / (1.f + __expf(-gg1)));
                *(float2*)&g_act[(size_t)rr * D_FF + c0] = o;
            }
        }
    }
}

// ---------------- flash DINT attention (exact R11 version, 187us proven) ----------
#define TQ 64
#define SROW 68  /* padded row stride in words */
#define FLASH_SMEM ((5 * 64 * SROW + 64 + 256) * 4)

__global__ void __launch_bounds__(256)
flash_attn(const float* __restrict__ lq1, const float* __restrict__ lq2,
           const float* __restrict__ lk1, const float* __restrict__ lk2,
           const float* __restrict__ hw, float lam_init) {
    extern __shared__ float sm[];
    float* Qs = sm;                 // 64*SROW
    float* Ks = Qs + 64 * SROW;
    float* Vs = Ks + 64 * SROW;
    float* S0 = Vs + 64 * SROW;
    float* S1 = S0 + 64 * SROW;
    float* oSful = S1 + 64 * SROW;  // 64
    float* vred  = oSful + 64;      // 256
    __shared__ float lam_sh;

    const int qt = (gridDim.x - 1) - blockIdx.x;   // heavy tiles first
    const int h  = blockIdx.y;
    const int b  = blockIdx.z;
    const int tid = threadIdx.x;
    const int tq0 = qt * TQ;

    if (tid == 0) {
        float a = 0.f, c = 0.f;
#pragma unroll
        for (int i = 0; i < HD2; i++) { a += lk1[i] * lq1[i]; c += lk2[i] * lq2[i]; }
        lam_sh = expf(a) - expf(c) + lam_init;
    }
    if (tid < 64) oSful[tid] = 0.f;

    // load Q tile (64 x 64)
    {
        const float* qb = g_q + ((size_t)(b * T_FULL + tq0)) * D_MODEL + h * 64;
        for (int i = tid; i < 64 * 16; i += 256) {
            int r = i >> 4, c4 = (i & 15) * 4;
            *(float4*)&Qs[r * SROW + c4] = *(const float4*)(qb + (size_t)r * D_MODEL + c4);
        }
    }
    __syncthreads();

    const int qq = tid >> 2;             // 0..63 local query
    const int qi = tq0 + qq;             // global query
    const int ds = (tid & 3) * 16;       // 16-dim slice
    const int qg = tid >> 4;             // 0..15
    const int kg = tid & 15;             // 0..15

    ull o0p[8], o1p[8], oSp[8];
#pragma unroll
    for (int d = 0; d < 8; d++) { o0p[d] = 0ull; o1p[d] = 0ull; oSp[d] = 0ull; }
    float m0 = -INFINITY, l0 = 0.f, m1 = -INFINITY, l1 = 0.f;
    const float scale = 0.17677669529663687f; // 1/sqrt(32)

    for (int k0 = 0; k0 <= tq0; k0 += 64) {
        const bool diag = (k0 == tq0);
        {
            const float* kb = g_k + ((size_t)(b * T_FULL + k0)) * D_MODEL + h * 64;
            const float* vb = g_v + ((size_t)(b * T_FULL + k0)) * D_MODEL + h * 64;
            for (int i = tid; i < 64 * 16; i += 256) {
                int r = i >> 4, c4 = (i & 15) * 4;
                *(float4*)&Ks[r * SROW + c4] = *(const float4*)(kb + (size_t)r * D_MODEL + c4);
                *(float4*)&Vs[r * SROW + c4] = *(const float4*)(vb + (size_t)r * D_MODEL + c4);
            }
        }
        __syncthreads();

        // scores sub-head 0 (dims 0..31)
        {
            ull sp[4][4];
#pragma unroll
            for (int i = 0; i < 4; i++)
#pragma unroll
                for (int j = 0; j < 4; j++) sp[i][j] = 0ull;
#pragma unroll
            for (int d = 0; d < 32; d += 4) {
                ulonglong2 qr[4], kr[4];
#pragma unroll
                for (int i = 0; i < 4; i++) qr[i] = *(const ulonglong2*)&Qs[(qg + 16 * i) * SROW + d];
#pragma unroll
                for (int j = 0; j < 4; j++) kr[j] = *(const ulonglong2*)&Ks[(kg + 16 * j) * SROW + d];
#pragma unroll
                for (int i = 0; i < 4; i++)
#pragma unroll
                    for (int j = 0; j < 4; j++) {
                        sp[i][j] = ffma2(qr[i].x, kr[j].x, sp[i][j]);
                        sp[i][j] = ffma2(qr[i].y, kr[j].y, sp[i][j]);
                    }
            }
#pragma unroll
            for (int i = 0; i < 4; i++)
#pragma unroll
                for (int j = 0; j < 4; j++) {
                    int qrow = qg + 16 * i, krow = kg + 16 * j;
                    bool ok = (k0 + krow) <= (tq0 + qrow);
                    float2 f = funpack2(sp[i][j]);
                    S0[qrow * SROW + krow] = ok ? (f.x + f.y) * scale : -INFINITY;
                }
        }
        // scores sub-head 1 (dims 32..63)
        {
            ull sp[4][4];
#pragma unroll
            for (int i = 0; i < 4; i++)
#pragma unroll
                for (int j = 0; j < 4; j++) sp[i][j] = 0ull;
#pragma unroll
            for (int d = 32; d < 64; d += 4) {
                ulonglong2 qr[4], kr[4];
#pragma unroll
                for (int i = 0; i < 4; i++) qr[i] = *(const ulonglong2*)&Qs[(qg + 16 * i) * SROW + d];
#pragma unroll
                for (int j = 0; j < 4; j++) kr[j] = *(const ulonglong2*)&Ks[(kg + 16 * j) * SROW + d];
#pragma unroll
                for (int i = 0; i < 4; i++)
#pragma unroll
                    for (int j = 0; j < 4; j++) {
                        sp[i][j] = ffma2(qr[i].x, kr[j].x, sp[i][j]);
                        sp[i][j] = ffma2(qr[i].y, kr[j].y, sp[i][j]);
                    }
            }
#pragma unroll
            for (int i = 0; i < 4; i++)
#pragma unroll
                for (int j = 0; j < 4; j++) {
                    int qrow = qg + 16 * i, krow = kg + 16 * j;
                    bool ok = (k0 + krow) <= (tq0 + qrow);
                    float2 f = funpack2(sp[i][j]);
                    S1[qrow * SROW + krow] = ok ? (f.x + f.y) * scale : -INFINITY;
                }
        }
        __syncthreads();

        // stats + exp (register-buffered — R11 proven)
        {
            const int kb0 = (tid & 3) * 16;
            float sv0[16], sv1[16];
            float tm0 = -INFINITY, tm1 = -INFINITY;
#pragma unroll
            for (int k = 0; k < 16; k++) {
                sv0[k] = S0[qq * SROW + kb0 + k];
                sv1[k] = S1[qq * SROW + kb0 + k];
                tm0 = fmaxf(tm0, sv0[k]);
                tm1 = fmaxf(tm1, sv1[k]);
            }
            tm0 = fmaxf(tm0, __shfl_xor_sync(0xffffffffu, tm0, 1));
            tm0 = fmaxf(tm0, __shfl_xor_sync(0xffffffffu, tm0, 2));
            tm1 = fmaxf(tm1, __shfl_xor_sync(0xffffffffu, tm1, 1));
            tm1 = fmaxf(tm1, __shfl_xor_sync(0xffffffffu, tm1, 2));
            float nm0 = fmaxf(m0, tm0), nm1 = fmaxf(m1, tm1);
            float ts0 = 0.f, ts1 = 0.f;
#pragma unroll
            for (int k = 0; k < 16; k++) {
                float p0 = __expf(sv0[k] - nm0);
                float p1 = __expf(sv1[k] - nm1);
                ts0 += p0; ts1 += p1;
                S0[qq * SROW + kb0 + k] = p0;
                S1[qq * SROW + kb0 + k] = p1;
            }
            ts0 += __shfl_xor_sync(0xffffffffu, ts0, 1);
            ts0 += __shfl_xor_sync(0xffffffffu, ts0, 2);
            ts1 += __shfl_xor_sync(0xffffffffu, ts1, 1);
            ts1 += __shfl_xor_sync(0xffffffffu, ts1, 2);
            float r0 = __expf(m0 - nm0), r1 = __expf(m1 - nm1);
            l0 = l0 * r0 + ts0; m0 = nm0;
            l1 = l1 * r1 + ts1; m1 = nm1;
            ull r0d = fpack2(r0, r0), r1d = fpack2(r1, r1);
#pragma unroll
            for (int d = 0; d < 8; d++) { o0p[d] = fmul2(r0d, o0p[d]); o1p[d] = fmul2(r1d, o1p[d]); }
        }
        // cooperative tile V-sum partials (full tiles only)
        if (!diag) {
            const int c = tid >> 6, d = tid & 63;
            float s = 0.f;
#pragma unroll
            for (int kk = 0; kk < 16; kk++) s += Vs[(c * 16 + kk) * SROW + d];
            vred[tid] = s;
        }
        __syncthreads();

        // AV accumulate (packed f32x2)
        if (!diag) {
            if (tid < 64)
                oSful[tid] += vred[tid] + vred[64 + tid] + vred[128 + tid] + vred[192 + tid];
            for (int k = 0; k < 64; k++) {
                float p0 = S0[qq * SROW + k];
                float p1 = S1[qq * SROW + k];
                ull pd0 = fpack2(p0, p0), pd1 = fpack2(p1, p1);
                const ulonglong2* vp = (const ulonglong2*)&Vs[k * SROW + ds];
#pragma unroll
                for (int d4 = 0; d4 < 4; d4++) {
                    ulonglong2 v = vp[d4];
                    o0p[2 * d4 + 0] = ffma2(pd0, v.x, o0p[2 * d4 + 0]);
                    o0p[2 * d4 + 1] = ffma2(pd0, v.y, o0p[2 * d4 + 1]);
                    o1p[2 * d4 + 0] = ffma2(pd1, v.x, o1p[2 * d4 + 0]);
                    o1p[2 * d4 + 1] = ffma2(pd1, v.y, o1p[2 * d4 + 1]);
                }
            }
        } else {
            for (int k = 0; k < 64; k++) {
                float p0 = S0[qq * SROW + k];
                float p1 = S1[qq * SROW + k];
                ull pd0 = fpack2(p0, p0), pd1 = fpack2(p1, p1);
                bool ok = (k0 + k) <= qi;
                const ulonglong2* vp = (const ulonglong2*)&Vs[k * SROW + ds];
#pragma unroll
                for (int d4 = 0; d4 < 4; d4++) {
                    ulonglong2 v = vp[d4];
                    o0p[2 * d4 + 0] = ffma2(pd0, v.x, o0p[2 * d4 + 0]);
                    o0p[2 * d4 + 1] = ffma2(pd0, v.y, o0p[2 * d4 + 1]);
                    o1p[2 * d4 + 0] = ffma2(pd1, v.x, o1p[2 * d4 + 0]);
                    o1p[2 * d4 + 1] = ffma2(pd1, v.y, o1p[2 * d4 + 1]);
                    if (ok) {
                        oSp[2 * d4 + 0] = fadd2(oSp[2 * d4 + 0], v.x);
                        oSp[2 * d4 + 1] = fadd2(oSp[2 * d4 + 1], v.y);
                    }
                }
            }
        }
        __syncthreads();
    }

    // epilogue: combine, per-head RMS, write (B,H,T,HD) layout
    {
        float lam = lam_sh;
        float inv0 = 1.f / l0, inv1 = 1.f / l1;
        float coef = lam / (float)(qi + 1);
        float outv[16];
        float ss = 0.f;
#pragma unroll
        for (int p = 0; p < 8; p++) {
            float2 a0 = funpack2(o0p[p]);
            float2 a1 = funpack2(o1p[p]);
            float2 aS = funpack2(oSp[p]);
            int d0 = 2 * p;
            outv[d0 + 0] = a0.x * inv0 - lam * (a1.x * inv1) + coef * (oSful[ds + d0 + 0] + aS.x);
            outv[d0 + 1] = a0.y * inv0 - lam * (a1.y * inv1) + coef * (oSful[ds + d0 + 1] + aS.y);
            ss += outv[d0 + 0] * outv[d0 + 0] + outv[d0 + 1] * outv[d0 + 1];
        }
        ss += __shfl_xor_sync(0xffffffffu, ss, 1);
        ss += __shfl_xor_sync(0xffffffffu, ss, 2);
        float rinv_ = rsqrtf(ss / 64.f + EPS_HEAD);
        float* yb = g_y + (((size_t)(b * NHEAD + h)) * T_FULL + qi) * HD + ds;
#pragma unroll
        for (int d4 = 0; d4 < 4; d4++) {
            float4 w;
            w.x = outv[d4 * 4 + 0] * rinv_ * hw[ds + d4 * 4 + 0];
            w.y = outv[d4 * 4 + 1] * rinv_ * hw[ds + d4 * 4 + 1];
            w.z = outv[d4 * 4 + 2] * rinv_ * hw[ds + d4 * 4 + 2];
            w.w = outv[d4 * 4 + 3] * rinv_ * hw[ds + d4 * 4 + 3];
            *(float4*)&yb[d4 * 4] = w;
        }
    }
}

// ---------------- final head ------------------------------------------------------
__global__ void final_kernel(const float* __restrict__ nfw, const float* __restrict__ Wp,
                             const float* __restrict__ bp, float* __restrict__ out) {
    int row = blockIdx.x;
    int t = threadIdx.x;
    __shared__ float red[256];
    const float* hr = g_h + (size_t)row * D_MODEL;
    float ss = 0.f;
    for (int dd = t; dd < D_MODEL; dd += 256) { float v = hr[dd]; ss += v * v; }
    red[t] = ss;
    __syncthreads();
    for (int s = 128; s > 0; s >>= 1) {
        if (t < s) red[t] += red[t + s];
        __syncthreads();
    }
    float inv = rsqrtf(red[0] / (float)D_MODEL + EPS_DEF);
    __syncthreads();
    for (int p = 0; p < 4; p++) {
        float acc = 0.f;
        for (int dd = t; dd < D_MODEL; dd += 256)
            acc += hr[dd] * inv * nfw[dd] * Wp[p * D_MODEL + dd];
        red[t] = acc;
        __syncthreads();
        for (int s = 128; s > 0; s >>= 1) {
            if (t < s) red[t] += red[t + s];
            __syncthreads();
        }
        if (t == 0) out[row * 4 + p] = red[0] + bp[p];
        __syncthreads();
    }
}

// ---------------- orchestration ----------------------------------------------------
extern "C" void kernel_launch(void* const* d_in, const int* in_sizes, int n_in,
                              void* d_out, int out_size) {
    const float* x       = (const float*)d_in[0];
    const int*   sep     = (const int*)  d_in[1];
    const float* Wq      = (const float*)d_in[2];
    const float* bq      = (const float*)d_in[3];
    const float* Wk      = (const float*)d_in[4];
    const float* bk      = (const float*)d_in[5];
    const float* Wv      = (const float*)d_in[6];
    const float* bv      = (const float*)d_in[7];
    const float* Wo      = (const float*)d_in[8];
    const float* bo      = (const float*)d_in[9];
    const float* lq1     = (const float*)d_in[10];
    const float* lq2     = (const float*)d_in[11];
    const float* lk1     = (const float*)d_in[12];
    const float* lk2     = (const float*)d_in[13];
    const float* hw      = (const float*)d_in[14];
    const float* n1w     = (const float*)d_in[15];
    const float* n2w     = (const float*)d_in[16];
    const float* Wg      = (const float*)d_in[17];
    const float* bg      = (const float*)d_in[18];
    const float* Wf      = (const float*)d_in[19];
    const float* bf      = (const float*)d_in[20];
    const float* Wi      = (const float*)d_in[21];
    const float* bi      = (const float*)d_in[22];
    const float* nfw     = (const float*)d_in[23];
    const float* Wp      = (const float*)d_in[24];
    const float* bp      = (const float*)d_in[25];
    const float* sep_emb = (const float*)d_in[26];
    const float* cosb    = (const float*)d_in[27];
    const float* sinb    = (const float*)d_in[28];

    float *h, *q, *k, *v, *y, *act, *rinv;
    cudaGetSymbolAddress((void**)&h,  g_h);
    cudaGetSymbolAddress((void**)&q,  g_q);
    cudaGetSymbolAddress((void**)&k,  g_k);
    cudaGetSymbolAddress((void**)&v,  g_v);
    cudaGetSymbolAddress((void**)&y,  g_y);
    cudaGetSymbolAddress((void**)&act, g_act);
    cudaGetSymbolAddress((void**)&rinv, g_rinv);

    cudaFuncSetAttribute(flash_attn, cudaFuncAttributeMaxDynamicSharedMemorySize, FLASH_SMEM);

    embed_kernel<<<ROWS, 256>>>(x, sep, sep_emb, Wi, bi);

    const dim3 gQKV(48, ROWS / 128);                // 48 x 8 = 384 blocks
    const dim3 gWo(D_MODEL / 64, ROWS / 64);        // 16 x 16 = 256 blocks
    const dim3 gF1(D_FF / 64, ROWS / 64);           // 44 x 16 = 704 blocks
    const dim3 gA(T_FULL / TQ, NHEAD, BATCH);       // 8 x 16 x 2

    for (int l = 0; l < 6; l++) {
        float lam_init = (float)(0.8 - 0.6 * exp(-0.3 * (double)l));

        rms_stat<<<ROWS, 256>>>(h, rinv, EPS_DEF);

        gemm_qkv<<<gQKV, 256>>>(h,
                                Wq + (size_t)l * D_MODEL * D_MODEL,
                                Wk + (size_t)l * D_MODEL * D_MODEL,
                                Wv + (size_t)l * D_MODEL * D_MODEL,
                                bq + l * D_MODEL, bk + l * D_MODEL, bv + l * D_MODEL,
                                cosb, sinb, rinv, n1w + l * D_MODEL);

        flash_attn<<<gA, 256, FLASH_SMEM>>>(
            lq1 + l * HD2, lq2 + l * HD2, lk1 + l * HD2, lk2 + l * HD2,
            hw + l * HD, lam_init);

        gemm_small<<<gWo, 128>>>(y, Wo + (size_t)l * D_MODEL * D_MODEL, bo + l * D_MODEL,
                                 h, D_MODEL, D_MODEL, 1);

        rms_stat<<<ROWS, 256>>>(h, rinv, EPS_DEF);

        gemm_ffn1<<<gF1, 128>>>(h, Wg + (size_t)l * 2 * D_FF * D_MODEL,
                                bg + (size_t)l * 2 * D_FF,
                                rinv, n2w + l * D_MODEL);

        gemm_small<<<gWo, 128>>>(act, Wf + (size_t)l * D_FF * D_MODEL,
                                 bf + l * D_MODEL, h, D_MODEL, D_FF, 1);
    }

    final_kernel<<<ROWS, 256>>>(nfw, Wp, bp, (float*)d_out);
}

// round 17
// speedup vs baseline: 1.0798x; 1.0798x over previous
#include <cuda_runtime.h>
#include <math.h>

#define D_MODEL 1024
#define T_FULL 512
#define BATCH 2
#define ROWS (BATCH * T_FULL)   /* 1024 */
#define D_FF 2816
#define IN_FEAT 64
#define NHEAD 16
#define HD 64
#define HD2 32
#define EPS_DEF 1.1920928955078125e-07f
#define EPS_HEAD 1e-05f

typedef unsigned long long ull;

// ---------------- packed f32x2 helpers (sm_103a FFMA2 path) -----------------------
__device__ __forceinline__ ull ffma2(ull a, ull b, ull c) {
    ull r; asm("fma.rn.f32x2 %0, %1, %2, %3;" : "=l"(r) : "l"(a), "l"(b), "l"(c)); return r;
}
__device__ __forceinline__ ull fmul2(ull a, ull b) {
    ull r; asm("mul.rn.f32x2 %0, %1, %2;" : "=l"(r) : "l"(a), "l"(b)); return r;
}
__device__ __forceinline__ ull fadd2(ull a, ull b) {
    ull r; asm("add.rn.f32x2 %0, %1, %2;" : "=l"(r) : "l"(a), "l"(b)); return r;
}
__device__ __forceinline__ ull fpack2(float lo, float hi) {
    ull r; asm("mov.b64 %0, {%1, %2};" : "=l"(r) : "f"(lo), "f"(hi)); return r;
}
__device__ __forceinline__ float2 funpack2(ull v) {
    float2 f; asm("mov.b64 {%0, %1}, %2;" : "=f"(f.x), "=f"(f.y) : "l"(v)); return f;
}

// ---------------- scratch (device globals; no allocation allowed) ----------------
__device__ float g_h [ROWS * D_MODEL];
__device__ float g_xn[ROWS * D_MODEL];
__device__ float g_q [ROWS * D_MODEL];
__device__ float g_k [ROWS * D_MODEL];
__device__ float g_v [ROWS * D_MODEL];
__device__ float g_y [ROWS * D_MODEL];
__device__ float g_act[ROWS * D_FF];

// ---------------- embed ----------------------------------------------------------
__global__ void embed_kernel(const float* __restrict__ x, const int* __restrict__ sep,
                             const float* __restrict__ sep_emb,
                             const float* __restrict__ Wi, const float* __restrict__ bi) {
    int row = blockIdx.x;
    int b = row >> 9;
    int t = row & 511;
    const float inv = 0.03125f; // 1/sqrt(1024)
    if (t == 0) {
        int idx = sep[b];
        for (int d = threadIdx.x; d < D_MODEL; d += blockDim.x)
            g_h[row * D_MODEL + d] = sep_emb[idx * D_MODEL + d] * inv;
        return;
    }
    __shared__ float xs[IN_FEAT];
    if (threadIdx.x < IN_FEAT)
        xs[threadIdx.x] = x[(b * 511 + (t - 1)) * IN_FEAT + threadIdx.x];
    __syncthreads();
    for (int d = threadIdx.x; d < D_MODEL; d += blockDim.x) {
        float acc = bi[d];
        const float* wr = Wi + d * IN_FEAT;
#pragma unroll
        for (int f = 0; f < IN_FEAT; f++) acc += xs[f] * wr[f];
        g_h[row * D_MODEL + d] = acc * inv;
    }
}

// ---------------- RMSNorm (shuffle reduction; data held in registers) -------------
// 256 threads, each owns exactly one float4 of the 1024-wide row.
__global__ void rms_kernel(const float* __restrict__ in, const float* __restrict__ w,
                           float* __restrict__ out, float eps) {
    const int row = blockIdx.x;
    const int t = threadIdx.x;
    __shared__ float ws[8];
    __shared__ float inv_sh;

    float4 v = ((const float4*)(in + (size_t)row * D_MODEL))[t];
    float ss = v.x * v.x + v.y * v.y + v.z * v.z + v.w * v.w;
#pragma unroll
    for (int off = 16; off > 0; off >>= 1)
        ss += __shfl_xor_sync(0xffffffffu, ss, off);
    if ((t & 31) == 0) ws[t >> 5] = ss;
    __syncthreads();
    if (t == 0) {
        float s = ws[0] + ws[1] + ws[2] + ws[3] + ws[4] + ws[5] + ws[6] + ws[7];
        inv_sh = rsqrtf(s / (float)D_MODEL + eps);
    }
    __syncthreads();
    const float inv = inv_sh;
    float4 w4 = ((const float4*)w)[t];
    float4 o;
    o.x = v.x * inv * w4.x;
    o.y = v.y * inv * w4.y;
    o.z = v.z * inv * w4.z;
    o.w = v.w * inv * w4.w;
    ((float4*)(out + (size_t)row * D_MODEL))[t] = o;
}

// ---------------- TF32 tensor-core GEMM (single-buffered, R9/R11-proven) ----------
#define BK 32
#define BKP 36

__device__ __forceinline__ unsigned f2tf32(float x) {
    unsigned y;
    asm("cvt.rna.tf32.f32 %0, %1;" : "=r"(y) : "f"(x));
    return y;
}

// C[M,N] = A[M,K] @ W[N,K]^T + bias (+C if accum); optional fused interleaved RoPE.
template <int TBM, int TBN, int NT>
__device__ __forceinline__ void gemm_body(
    const float* __restrict__ A, const float* __restrict__ W,
    const float* __restrict__ bias, float* __restrict__ C,
    int N, int K, int accum, int bm, int bn,
    int do_rope, const float* __restrict__ cosb, const float* __restrict__ sinb) {
    __shared__ unsigned As[TBM * BKP];
    __shared__ unsigned Ws[TBN * BKP];

    constexpr int WN  = TBN / 32;           // warps along n
    constexpr int AIT = TBM * 8 / NT;       // A load iters (float4)
    constexpr int BIT = TBN * 8 / NT;       // B load iters

    const int tid  = threadIdx.x;
    const int lane = tid & 31;
    const int wid  = tid >> 5;
    const int wm   = wid / WN;
    const int wn   = wid % WN;
    const int gid  = lane >> 2;
    const int tig  = lane & 3;

    float acc[2][4][4];
#pragma unroll
    for (int mt = 0; mt < 2; mt++)
#pragma unroll
        for (int nt = 0; nt < 4; nt++)
#pragma unroll
            for (int r = 0; r < 4; r++) acc[mt][nt][r] = 0.f;

    float4 ra[AIT], rb[BIT];
    const int pcol = (tid & 7) * 4;

    auto ldg_tile = [&](int k0) {
#pragma unroll
        for (int i = 0; i < AIT; i++) {
            int r = (tid + i * NT) >> 3;
            ra[i] = *(const float4*)(A + (size_t)(bm + r) * K + k0 + pcol);
        }
#pragma unroll
        for (int i = 0; i < BIT; i++) {
            int r = (tid + i * NT) >> 3;
            rb[i] = *(const float4*)(W + (size_t)(bn + r) * K + k0 + pcol);
        }
    };
    auto sts_tile = [&]() {
#pragma unroll
        for (int i = 0; i < AIT; i++) {
            int r = (tid + i * NT) >> 3;
            uint4 u = { f2tf32(ra[i].x), f2tf32(ra[i].y), f2tf32(ra[i].z), f2tf32(ra[i].w) };
            *(uint4*)&As[r * BKP + pcol] = u;
        }
#pragma unroll
        for (int i = 0; i < BIT; i++) {
            int r = (tid + i * NT) >> 3;
            uint4 u = { f2tf32(rb[i].x), f2tf32(rb[i].y), f2tf32(rb[i].z), f2tf32(rb[i].w) };
            *(uint4*)&Ws[r * BKP + pcol] = u;
        }
    };

    ldg_tile(0);
    sts_tile();
    __syncthreads();

    const int nit = K / BK;
    for (int it = 0; it < nit; it++) {
        if (it + 1 < nit) ldg_tile((it + 1) * BK);

#pragma unroll
        for (int ks = 0; ks < 4; ks++) {
            const int k = ks * 8;
            unsigned af[2][4], bf[4][2];
#pragma unroll
            for (int mt = 0; mt < 2; mt++) {
                int r = wm * 32 + mt * 16 + gid;
                af[mt][0] = As[r * BKP + k + tig];
                af[mt][1] = As[(r + 8) * BKP + k + tig];
                af[mt][2] = As[r * BKP + k + tig + 4];
                af[mt][3] = As[(r + 8) * BKP + k + tig + 4];
            }
#pragma unroll
            for (int nt = 0; nt < 4; nt++) {
                int c = wn * 32 + nt * 8 + gid;
                bf[nt][0] = Ws[c * BKP + k + tig];
                bf[nt][1] = Ws[c * BKP + k + tig + 4];
            }
#pragma unroll
            for (int mt = 0; mt < 2; mt++)
#pragma unroll
                for (int nt = 0; nt < 4; nt++) {
                    asm volatile(
                        "mma.sync.aligned.m16n8k8.row.col.f32.tf32.tf32.f32 "
                        "{%0,%1,%2,%3}, {%4,%5,%6,%7}, {%8,%9}, {%0,%1,%2,%3};\n"
                        : "+f"(acc[mt][nt][0]), "+f"(acc[mt][nt][1]),
                          "+f"(acc[mt][nt][2]), "+f"(acc[mt][nt][3])
                        : "r"(af[mt][0]), "r"(af[mt][1]), "r"(af[mt][2]), "r"(af[mt][3]),
                          "r"(bf[nt][0]), "r"(bf[nt][1]));
                }
        }
        __syncthreads();
        if (it + 1 < nit) {
            sts_tile();
            __syncthreads();
        }
    }

#pragma unroll
    for (int mt = 0; mt < 2; mt++) {
        int r0 = bm + wm * 32 + mt * 16 + gid;
#pragma unroll
        for (int nt = 0; nt < 4; nt++) {
            int c0 = bn + wn * 32 + nt * 8 + 2 * tig;
            float2 b2 = *(const float2*)(bias + c0);
            float* p0 = C + (size_t)r0 * N + c0;
            float* p1 = C + (size_t)(r0 + 8) * N + c0;
            float2 v0 = { acc[mt][nt][0] + b2.x, acc[mt][nt][1] + b2.y };
            float2 v1 = { acc[mt][nt][2] + b2.x, acc[mt][nt][3] + b2.y };
            if (accum) {
                float2 o0 = *(float2*)p0, o1 = *(float2*)p1;
                v0.x += o0.x; v0.y += o0.y;
                v1.x += o1.x; v1.y += o1.y;
            }
            if (do_rope) {
                int i = (c0 & 31) >> 1;    // pair index within sub-head
                int t0 = r0 & 511;
                if (t0 > 0) {
                    float cc = cosb[(t0 - 1) * 16 + i], ss = sinb[(t0 - 1) * 16 + i];
                    float xr = v0.x, xi = v0.y;
                    v0.x = xr * cc - xi * ss;
                    v0.y = xr * ss + xi * cc;
                }
                int t1 = (r0 + 8) & 511;
                if (t1 > 0) {
                    float cc = cosb[(t1 - 1) * 16 + i], ss = sinb[(t1 - 1) * 16 + i];
                    float xr = v1.x, xi = v1.y;
                    v1.x = xr * cc - xi * ss;
                    v1.y = xr * ss + xi * cc;
                }
            }
            *(float2*)p0 = v0;
            *(float2*)p1 = v1;
        }
    }
}

// 128x64 tile, 256 threads — QKV with fused RoPE
__global__ void __launch_bounds__(256)
gemm_qkv(const float* __restrict__ A,
         const float* __restrict__ Wq, const float* __restrict__ Wk, const float* __restrict__ Wv,
         const float* __restrict__ bq, const float* __restrict__ bk, const float* __restrict__ bv,
         const float* __restrict__ cosb, const float* __restrict__ sinb) {
    const int seg = blockIdx.x >> 4;               // 0..2
    const int bn = (blockIdx.x & 15) * 64;
    const float* W   = (seg == 0) ? Wq : (seg == 1) ? Wk : Wv;
    const float* bia = (seg == 0) ? bq : (seg == 1) ? bk : bv;
    float* C = (seg == 0) ? g_q : (seg == 1) ? g_k : g_v;
    gemm_body<128, 64, 256>(A, W, bia, C, D_MODEL, D_MODEL, 0, blockIdx.y * 128, bn,
                            (seg < 2) ? 1 : 0, cosb, sinb);
}

// 64x64 tile, 128 threads — Wo/Wf (grid 256 > SM count)
__global__ void __launch_bounds__(128)
gemm_small(const float* __restrict__ A, const float* __restrict__ W,
           const float* __restrict__ bias, float* __restrict__ C,
           int N, int K, int accum) {
    gemm_body<64, 64, 128>(A, W, bias, C, N, K, accum, blockIdx.y * 64, blockIdx.x * 64,
                           0, (const float*)0, (const float*)0);
}

// ---------------- fused FFN-1: act = u * silu(g), u/g from Wg halves --------------
__global__ void __launch_bounds__(128)
gemm_ffn1(const float* __restrict__ A, const float* __restrict__ Wg_,
          const float* __restrict__ bg_) {
    __shared__ unsigned As[64 * BKP];
    __shared__ unsigned Us[64 * BKP];
    __shared__ unsigned Gs[64 * BKP];

    const int tid  = threadIdx.x;
    const int lane = tid & 31;
    const int wid  = tid >> 5;
    const int wm   = wid >> 1;
    const int wn   = wid & 1;
    const int gid  = lane >> 2;
    const int tig  = lane & 3;
    const int bm   = blockIdx.y * 64;
    const int bn   = blockIdx.x * 64;

    float accU[2][4][4], accG[2][4][4];
#pragma unroll
    for (int mt = 0; mt < 2; mt++)
#pragma unroll
        for (int nt = 0; nt < 4; nt++)
#pragma unroll
            for (int r = 0; r < 4; r++) { accU[mt][nt][r] = 0.f; accG[mt][nt][r] = 0.f; }

    float4 ra[4], ru[4], rg[4];
    const int pcol = (tid & 7) * 4;

    auto ldg_tile = [&](int k0) {
#pragma unroll
        for (int i = 0; i < 4; i++) {
            int r = (tid + i * 128) >> 3;
            ra[i] = *(const float4*)(A   + (size_t)(bm + r) * D_MODEL + k0 + pcol);
            ru[i] = *(const float4*)(Wg_ + (size_t)(bn + r) * D_MODEL + k0 + pcol);
            rg[i] = *(const float4*)(Wg_ + (size_t)(D_FF + bn + r) * D_MODEL + k0 + pcol);
        }
    };
    auto sts_tile = [&]() {
#pragma unroll
        for (int i = 0; i < 4; i++) {
            int r = (tid + i * 128) >> 3;
            uint4 ua = { f2tf32(ra[i].x), f2tf32(ra[i].y), f2tf32(ra[i].z), f2tf32(ra[i].w) };
            *(uint4*)&As[r * BKP + pcol] = ua;
            uint4 uu = { f2tf32(ru[i].x), f2tf32(ru[i].y), f2tf32(ru[i].z), f2tf32(ru[i].w) };
            *(uint4*)&Us[r * BKP + pcol] = uu;
            uint4 ug = { f2tf32(rg[i].x), f2tf32(rg[i].y), f2tf32(rg[i].z), f2tf32(rg[i].w) };
            *(uint4*)&Gs[r * BKP + pcol] = ug;
        }
    };

    ldg_tile(0);
    sts_tile();
    __syncthreads();

    const int nit = D_MODEL / BK;   // 32
    for (int it = 0; it < nit; it++) {
        if (it + 1 < nit) ldg_tile((it + 1) * BK);

#pragma unroll
        for (int ks = 0; ks < 4; ks++) {
            const int k = ks * 8;
            unsigned af[2][4], bu[4][2], bg2[4][2];
#pragma unroll
            for (int mt = 0; mt < 2; mt++) {
                int r = wm * 32 + mt * 16 + gid;
                af[mt][0] = As[r * BKP + k + tig];
                af[mt][1] = As[(r + 8) * BKP + k + tig];
                af[mt][2] = As[r * BKP + k + tig + 4];
                af[mt][3] = As[(r + 8) * BKP + k + tig + 4];
            }
#pragma unroll
            for (int nt = 0; nt < 4; nt++) {
                int c = wn * 32 + nt * 8 + gid;
                bu[nt][0]  = Us[c * BKP + k + tig];
                bu[nt][1]  = Us[c * BKP + k + tig + 4];
                bg2[nt][0] = Gs[c * BKP + k + tig];
                bg2[nt][1] = Gs[c * BKP + k + tig + 4];
            }
#pragma unroll
            for (int mt = 0; mt < 2; mt++)
#pragma unroll
                for (int nt = 0; nt < 4; nt++) {
                    asm volatile(
                        "mma.sync.aligned.m16n8k8.row.col.f32.tf32.tf32.f32 "
                        "{%0,%1,%2,%3}, {%4,%5,%6,%7}, {%8,%9}, {%0,%1,%2,%3};\n"
                        : "+f"(accU[mt][nt][0]), "+f"(accU[mt][nt][1]),
                          "+f"(accU[mt][nt][2]), "+f"(accU[mt][nt][3])
                        : "r"(af[mt][0]), "r"(af[mt][1]), "r"(af[mt][2]), "r"(af[mt][3]),
                          "r"(bu[nt][0]), "r"(bu[nt][1]));
                    asm volatile(
                        "mma.sync.aligned.m16n8k8.row.col.f32.tf32.tf32.f32 "
                        "{%0,%1,%2,%3}, {%4,%5,%6,%7}, {%8,%9}, {%0,%1,%2,%3};\n"
                        : "+f"(accG[mt][nt][0]), "+f"(accG[mt][nt][1]),
                          "+f"(accG[mt][nt][2]), "+f"(accG[mt][nt][3])
                        : "r"(af[mt][0]), "r"(af[mt][1]), "r"(af[mt][2]), "r"(af[mt][3]),
                          "r"(bg2[nt][0]), "r"(bg2[nt][1]));
                }
        }
        __syncthreads();
        if (it + 1 < nit) {
            sts_tile();
            __syncthreads();
        }
    }

#pragma unroll
    for (int mt = 0; mt < 2; mt++) {
        int r0 = bm + wm * 32 + mt * 16 + gid;
#pragma unroll
        for (int nt = 0; nt < 4; nt++) {
            int c0 = bn + wn * 32 + nt * 8 + 2 * tig;
            float2 bU = *(const float2*)(bg_ + c0);
            float2 bG = *(const float2*)(bg_ + D_FF + c0);
#pragma unroll
            for (int half = 0; half < 2; half++) {
                int rr = r0 + half * 8;
                float u0 = accU[mt][nt][2 * half + 0] + bU.x;
                float u1 = accU[mt][nt][2 * half + 1] + bU.y;
                float gg0 = accG[mt][nt][2 * half + 0] + bG.x;
                float gg1 = accG[mt][nt][2 * half + 1] + bG.y;
                float2 o;
                o.x = u0 * (gg0 / (1.f + __expf(-gg0)));
                o.y = u1 * (gg1 / (1.f + __expf(-gg1)));
                *(float2*)&g_act[(size_t)rr * D_FF + c0] = o;
            }
        }
    }
}

// ---------------- flash DINT attention (exact R11 version, 187us proven) ----------
#define TQ 64
#define SROW 68  /* padded row stride in words */
#define FLASH_SMEM ((5 * 64 * SROW + 64 + 256) * 4)

__global__ void __launch_bounds__(256)
flash_attn(const float* __restrict__ lq1, const float* __restrict__ lq2,
           const float* __restrict__ lk1, const float* __restrict__ lk2,
           const float* __restrict__ hw, float lam_init) {
    extern __shared__ float sm[];
    float* Qs = sm;                 // 64*SROW
    float* Ks = Qs + 64 * SROW;
    float* Vs = Ks + 64 * SROW;
    float* S0 = Vs + 64 * SROW;
    float* S1 = S0 + 64 * SROW;
    float* oSful = S1 + 64 * SROW;  // 64
    float* vred  = oSful + 64;      // 256
    __shared__ float lam_sh;

    const int qt = (gridDim.x - 1) - blockIdx.x;   // heavy tiles first
    const int h  = blockIdx.y;
    const int b  = blockIdx.z;
    const int tid = threadIdx.x;
    const int tq0 = qt * TQ;

    if (tid == 0) {
        float a = 0.f, c = 0.f;
#pragma unroll
        for (int i = 0; i < HD2; i++) { a += lk1[i] * lq1[i]; c += lk2[i] * lq2[i]; }
        lam_sh = expf(a) - expf(c) + lam_init;
    }
    if (tid < 64) oSful[tid] = 0.f;

    // load Q tile (64 x 64)
    {
        const float* qb = g_q + ((size_t)(b * T_FULL + tq0)) * D_MODEL + h * 64;
        for (int i = tid; i < 64 * 16; i += 256) {
            int r = i >> 4, c4 = (i & 15) * 4;
            *(float4*)&Qs[r * SROW + c4] = *(const float4*)(qb + (size_t)r * D_MODEL + c4);
        }
    }
    __syncthreads();

    const int qq = tid >> 2;             // 0..63 local query
    const int qi = tq0 + qq;             // global query
    const int ds = (tid & 3) * 16;       // 16-dim slice
    const int qg = tid >> 4;             // 0..15
    const int kg = tid & 15;             // 0..15

    ull o0p[8], o1p[8], oSp[8];
#pragma unroll
    for (int d = 0; d < 8; d++) { o0p[d] = 0ull; o1p[d] = 0ull; oSp[d] = 0ull; }
    float m0 = -INFINITY, l0 = 0.f, m1 = -INFINITY, l1 = 0.f;
    const float scale = 0.17677669529663687f; // 1/sqrt(32)

    for (int k0 = 0; k0 <= tq0; k0 += 64) {
        const bool diag = (k0 == tq0);
        {
            const float* kb = g_k + ((size_t)(b * T_FULL + k0)) * D_MODEL + h * 64;
            const float* vb = g_v + ((size_t)(b * T_FULL + k0)) * D_MODEL + h * 64;
            for (int i = tid; i < 64 * 16; i += 256) {
                int r = i >> 4, c4 = (i & 15) * 4;
                *(float4*)&Ks[r * SROW + c4] = *(const float4*)(kb + (size_t)r * D_MODEL + c4);
                *(float4*)&Vs[r * SROW + c4] = *(const float4*)(vb + (size_t)r * D_MODEL + c4);
            }
        }
        __syncthreads();

        // scores sub-head 0 (dims 0..31)
        {
            ull sp[4][4];
#pragma unroll
            for (int i = 0; i < 4; i++)
#pragma unroll
                for (int j = 0; j < 4; j++) sp[i][j] = 0ull;
#pragma unroll
            for (int d = 0; d < 32; d += 4) {
                ulonglong2 qr[4], kr[4];
#pragma unroll
                for (int i = 0; i < 4; i++) qr[i] = *(const ulonglong2*)&Qs[(qg + 16 * i) * SROW + d];
#pragma unroll
                for (int j = 0; j < 4; j++) kr[j] = *(const ulonglong2*)&Ks[(kg + 16 * j) * SROW + d];
#pragma unroll
                for (int i = 0; i < 4; i++)
#pragma unroll
                    for (int j = 0; j < 4; j++) {
                        sp[i][j] = ffma2(qr[i].x, kr[j].x, sp[i][j]);
                        sp[i][j] = ffma2(qr[i].y, kr[j].y, sp[i][j]);
                    }
            }
#pragma unroll
            for (int i = 0; i < 4; i++)
#pragma unroll
                for (int j = 0; j < 4; j++) {
                    int qrow = qg + 16 * i, krow = kg + 16 * j;
                    bool ok = (k0 + krow) <= (tq0 + qrow);
                    float2 f = funpack2(sp[i][j]);
                    S0[qrow * SROW + krow] = ok ? (f.x + f.y) * scale : -INFINITY;
                }
        }
        // scores sub-head 1 (dims 32..63)
        {
            ull sp[4][4];
#pragma unroll
            for (int i = 0; i < 4; i++)
#pragma unroll
                for (int j = 0; j < 4; j++) sp[i][j] = 0ull;
#pragma unroll
            for (int d = 32; d < 64; d += 4) {
                ulonglong2 qr[4], kr[4];
#pragma unroll
                for (int i = 0; i < 4; i++) qr[i] = *(const ulonglong2*)&Qs[(qg + 16 * i) * SROW + d];
#pragma unroll
                for (int j = 0; j < 4; j++) kr[j] = *(const ulonglong2*)&Ks[(kg + 16 * j) * SROW + d];
#pragma unroll
                for (int i = 0; i < 4; i++)
#pragma unroll
                    for (int j = 0; j < 4; j++) {
                        sp[i][j] = ffma2(qr[i].x, kr[j].x, sp[i][j]);
                        sp[i][j] = ffma2(qr[i].y, kr[j].y, sp[i][j]);
                    }
            }
#pragma unroll
            for (int i = 0; i < 4; i++)
#pragma unroll
                for (int j = 0; j < 4; j++) {
                    int qrow = qg + 16 * i, krow = kg + 16 * j;
                    bool ok = (k0 + krow) <= (tq0 + qrow);
                    float2 f = funpack2(sp[i][j]);
                    S1[qrow * SROW + krow] = ok ? (f.x + f.y) * scale : -INFINITY;
                }
        }
        __syncthreads();

        // stats + exp (register-buffered)
        {
            const int kb0 = (tid & 3) * 16;
            float sv0[16], sv1[16];
            float tm0 = -INFINITY, tm1 = -INFINITY;
#pragma unroll
            for (int k = 0; k < 16; k++) {
                sv0[k] = S0[qq * SROW + kb0 + k];
                sv1[k] = S1[qq * SROW + kb0 + k];
                tm0 = fmaxf(tm0, sv0[k]);
                tm1 = fmaxf(tm1, sv1[k]);
            }
            tm0 = fmaxf(tm0, __shfl_xor_sync(0xffffffffu, tm0, 1));
            tm0 = fmaxf(tm0, __shfl_xor_sync(0xffffffffu, tm0, 2));
            tm1 = fmaxf(tm1, __shfl_xor_sync(0xffffffffu, tm1, 1));
            tm1 = fmaxf(tm1, __shfl_xor_sync(0xffffffffu, tm1, 2));
            float nm0 = fmaxf(m0, tm0), nm1 = fmaxf(m1, tm1);
            float ts0 = 0.f, ts1 = 0.f;
#pragma unroll
            for (int k = 0; k < 16; k++) {
                float p0 = __expf(sv0[k] - nm0);
                float p1 = __expf(sv1[k] - nm1);
                ts0 += p0; ts1 += p1;
                S0[qq * SROW + kb0 + k] = p0;
                S1[qq * SROW + kb0 + k] = p1;
            }
            ts0 += __shfl_xor_sync(0xffffffffu, ts0, 1);
            ts0 += __shfl_xor_sync(0xffffffffu, ts0, 2);
            ts1 += __shfl_xor_sync(0xffffffffu, ts1, 1);
            ts1 += __shfl_xor_sync(0xffffffffu, ts1, 2);
            float r0 = __expf(m0 - nm0), r1 = __expf(m1 - nm1);
            l0 = l0 * r0 + ts0; m0 = nm0;
            l1 = l1 * r1 + ts1; m1 = nm1;
            ull r0d = fpack2(r0, r0), r1d = fpack2(r1, r1);
#pragma unroll
            for (int d = 0; d < 8; d++) { o0p[d] = fmul2(r0d, o0p[d]); o1p[d] = fmul2(r1d, o1p[d]); }
        }
        // cooperative tile V-sum partials (full tiles only)
        if (!diag) {
            const int c = tid >> 6, d = tid & 63;
            float s = 0.f;
#pragma unroll
            for (int kk = 0; kk < 16; kk++) s += Vs[(c * 16 + kk) * SROW + d];
            vred[tid] = s;
        }
        __syncthreads();

        // AV accumulate (packed f32x2)
        if (!diag) {
            if (tid < 64)
                oSful[tid] += vred[tid] + vred[64 + tid] + vred[128 + tid] + vred[192 + tid];
            for (int k = 0; k < 64; k++) {
                float p0 = S0[qq * SROW + k];
                float p1 = S1[qq * SROW + k];
                ull pd0 = fpack2(p0, p0), pd1 = fpack2(p1, p1);
                const ulonglong2* vp = (const ulonglong2*)&Vs[k * SROW + ds];
#pragma unroll
                for (int d4 = 0; d4 < 4; d4++) {
                    ulonglong2 v = vp[d4];
                    o0p[2 * d4 + 0] = ffma2(pd0, v.x, o0p[2 * d4 + 0]);
                    o0p[2 * d4 + 1] = ffma2(pd0, v.y, o0p[2 * d4 + 1]);
                    o1p[2 * d4 + 0] = ffma2(pd1, v.x, o1p[2 * d4 + 0]);
                    o1p[2 * d4 + 1] = ffma2(pd1, v.y, o1p[2 * d4 + 1]);
                }
            }
        } else {
            for (int k = 0; k < 64; k++) {
                float p0 = S0[qq * SROW + k];
                float p1 = S1[qq * SROW + k];
                ull pd0 = fpack2(p0, p0), pd1 = fpack2(p1, p1);
                bool ok = (k0 + k) <= qi;
                const ulonglong2* vp = (const ulonglong2*)&Vs[k * SROW + ds];
#pragma unroll
                for (int d4 = 0; d4 < 4; d4++) {
                    ulonglong2 v = vp[d4];
                    o0p[2 * d4 + 0] = ffma2(pd0, v.x, o0p[2 * d4 + 0]);
                    o0p[2 * d4 + 1] = ffma2(pd0, v.y, o0p[2 * d4 + 1]);
                    o1p[2 * d4 + 0] = ffma2(pd1, v.x, o1p[2 * d4 + 0]);
                    o1p[2 * d4 + 1] = ffma2(pd1, v.y, o1p[2 * d4 + 1]);
                    if (ok) {
                        oSp[2 * d4 + 0] = fadd2(oSp[2 * d4 + 0], v.x);
                        oSp[2 * d4 + 1] = fadd2(oSp[2 * d4 + 1], v.y);
                    }
                }
            }
        }
        __syncthreads();
    }

    // epilogue: combine, per-head RMS, write (B,H,T,HD) layout
    {
        float lam = lam_sh;
        float inv0 = 1.f / l0, inv1 = 1.f / l1;
        float coef = lam / (float)(qi + 1);
        float outv[16];
        float ss = 0.f;
#pragma unroll
        for (int p = 0; p < 8; p++) {
            float2 a0 = funpack2(o0p[p]);
            float2 a1 = funpack2(o1p[p]);
            float2 aS = funpack2(oSp[p]);
            int d0 = 2 * p;
            outv[d0 + 0] = a0.x * inv0 - lam * (a1.x * inv1) + coef * (oSful[ds + d0 + 0] + aS.x);
            outv[d0 + 1] = a0.y * inv0 - lam * (a1.y * inv1) + coef * (oSful[ds + d0 + 1] + aS.y);
            ss += outv[d0 + 0] * outv[d0 + 0] + outv[d0 + 1] * outv[d0 + 1];
        }
        ss += __shfl_xor_sync(0xffffffffu, ss, 1);
        ss += __shfl_xor_sync(0xffffffffu, ss, 2);
        float rinv_ = rsqrtf(ss / 64.f + EPS_HEAD);
        float* yb = g_y + (((size_t)(b * NHEAD + h)) * T_FULL + qi) * HD + ds;
#pragma unroll
        for (int d4 = 0; d4 < 4; d4++) {
            float4 w;
            w.x = outv[d4 * 4 + 0] * rinv_ * hw[ds + d4 * 4 + 0];
            w.y = outv[d4 * 4 + 1] * rinv_ * hw[ds + d4 * 4 + 1];
            w.z = outv[d4 * 4 + 2] * rinv_ * hw[ds + d4 * 4 + 2];
            w.w = outv[d4 * 4 + 3] * rinv_ * hw[ds + d4 * 4 + 3];
            *(float4*)&yb[d4 * 4] = w;
        }
    }
}

// ---------------- final head (shuffle reduction; data held in registers) ----------
__global__ void final_kernel(const float* __restrict__ nfw, const float* __restrict__ Wp,
                             const float* __restrict__ bp, float* __restrict__ out) {
    const int row = blockIdx.x;
    const int t = threadIdx.x;
    __shared__ float ws[8];
    __shared__ float inv_sh;

    float4 v = ((const float4*)(g_h + (size_t)row * D_MODEL))[t];
    float ss = v.x * v.x + v.y * v.y + v.z * v.z + v.w * v.w;
#pragma unroll
    for (int off = 16; off > 0; off >>= 1)
        ss += __shfl_xor_sync(0xffffffffu, ss, off);
    if ((t & 31) == 0) ws[t >> 5] = ss;
    __syncthreads();
    if (t == 0) {
        float s = ws[0] + ws[1] + ws[2] + ws[3] + ws[4] + ws[5] + ws[6] + ws[7];
        inv_sh = rsqrtf(s / (float)D_MODEL + EPS_DEF);
    }
    __syncthreads();
    const float inv = inv_sh;
    float4 n4 = ((const float4*)nfw)[t];
    float4 hn;
    hn.x = v.x * inv * n4.x;
    hn.y = v.y * inv * n4.y;
    hn.z = v.z * inv * n4.z;
    hn.w = v.w * inv * n4.w;

    for (int p = 0; p < 4; p++) {
        float4 w4 = ((const float4*)(Wp + (size_t)p * D_MODEL))[t];
        float acc = hn.x * w4.x + hn.y * w4.y + hn.z * w4.z + hn.w * w4.w;
#pragma unroll
        for (int off = 16; off > 0; off >>= 1)
            acc += __shfl_xor_sync(0xffffffffu, acc, off);
        if ((t & 31) == 0) ws[t >> 5] = acc;
        __syncthreads();
        if (t == 0) {
            float s = ws[0] + ws[1] + ws[2] + ws[3] + ws[4] + ws[5] + ws[6] + ws[7];
            out[row * 4 + p] = s + bp[p];
        }
        __syncthreads();
    }
}

// ---------------- orchestration ----------------------------------------------------
extern "C" void kernel_launch(void* const* d_in, const int* in_sizes, int n_in,
                              void* d_out, int out_size) {
    const float* x       = (const float*)d_in[0];
    const int*   sep     = (const int*)  d_in[1];
    const float* Wq      = (const float*)d_in[2];
    const float* bq      = (const float*)d_in[3];
    const float* Wk      = (const float*)d_in[4];
    const float* bk      = (const float*)d_in[5];
    const float* Wv      = (const float*)d_in[6];
    const float* bv      = (const float*)d_in[7];
    const float* Wo      = (const float*)d_in[8];
    const float* bo      = (const float*)d_in[9];
    const float* lq1     = (const float*)d_in[10];
    const float* lq2     = (const float*)d_in[11];
    const float* lk1     = (const float*)d_in[12];
    const float* lk2     = (const float*)d_in[13];
    const float* hw      = (const float*)d_in[14];
    const float* n1w     = (const float*)d_in[15];
    const float* n2w     = (const float*)d_in[16];
    const float* Wg      = (const float*)d_in[17];
    const float* bg      = (const float*)d_in[18];
    const float* Wf      = (const float*)d_in[19];
    const float* bf      = (const float*)d_in[20];
    const float* Wi      = (const float*)d_in[21];
    const float* bi      = (const float*)d_in[22];
    const float* nfw     = (const float*)d_in[23];
    const float* Wp      = (const float*)d_in[24];
    const float* bp      = (const float*)d_in[25];
    const float* sep_emb = (const float*)d_in[26];
    const float* cosb    = (const float*)d_in[27];
    const float* sinb    = (const float*)d_in[28];

    float *h, *xn, *q, *k, *v, *y, *act;
    cudaGetSymbolAddress((void**)&h,  g_h);
    cudaGetSymbolAddress((void**)&xn, g_xn);
    cudaGetSymbolAddress((void**)&q,  g_q);
    cudaGetSymbolAddress((void**)&k,  g_k);
    cudaGetSymbolAddress((void**)&v,  g_v);
    cudaGetSymbolAddress((void**)&y,  g_y);
    cudaGetSymbolAddress((void**)&act, g_act);

    cudaFuncSetAttribute(flash_attn, cudaFuncAttributeMaxDynamicSharedMemorySize, FLASH_SMEM);

    embed_kernel<<<ROWS, 256>>>(x, sep, sep_emb, Wi, bi);

    const dim3 gQKV(48, ROWS / 128);                // 48 x 8 = 384 blocks
    const dim3 gWo(D_MODEL / 64, ROWS / 64);        // 16 x 16 = 256 blocks
    const dim3 gF1(D_FF / 64, ROWS / 64);           // 44 x 16 = 704 blocks
    const dim3 gA(T_FULL / TQ, NHEAD, BATCH);       // 8 x 16 x 2

    for (int l = 0; l < 6; l++) {
        float lam_init = (float)(0.8 - 0.6 * exp(-0.3 * (double)l));

        rms_kernel<<<ROWS, 256>>>(h, n1w + l * D_MODEL, xn, EPS_DEF);

        gemm_qkv<<<gQKV, 256>>>(xn,
                                Wq + (size_t)l * D_MODEL * D_MODEL,
                                Wk + (size_t)l * D_MODEL * D_MODEL,
                                Wv + (size_t)l * D_MODEL * D_MODEL,
                                bq + l * D_MODEL, bk + l * D_MODEL, bv + l * D_MODEL,
                                cosb, sinb);

        flash_attn<<<gA, 256, FLASH_SMEM>>>(
            lq1 + l * HD2, lq2 + l * HD2, lk1 + l * HD2, lk2 + l * HD2,
            hw + l * HD, lam_init);

        gemm_small<<<gWo, 128>>>(y, Wo + (size_t)l * D_MODEL * D_MODEL, bo + l * D_MODEL,
                                 h, D_MODEL, D_MODEL, 1);

        rms_kernel<<<ROWS, 256>>>(h, n2w + l * D_MODEL, xn, EPS_DEF);

        gemm_ffn1<<<gF1, 128>>>(xn, Wg + (size_t)l * 2 * D_FF * D_MODEL,
                                bg + (size_t)l * 2 * D_FF);

        gemm_small<<<gWo, 128>>>(act, Wf + (size_t)l * D_FF * D_MODEL,
                                 bf + l * D_MODEL, h, D_MODEL, D_FF, 1);
    }

    final_kernel<<<ROWS, 256>>>(nfw, Wp, bp, (float*)d_out);
}